// round 2
// baseline (speedup 1.0000x reference)
#include <cuda_runtime.h>

#define DT 0.05f
#define N_STEPS 41
#define TPB 256
#define MAX_BLOCKS 8192

// Per-block partial sums: [2*b] = sum(err+eff), [2*b+1] = sum(nor)
__device__ float g_partials[2 * MAX_BLOCKS];

__device__ __forceinline__ float fast_tanh(float x) {
    float y;
    asm("tanh.approx.f32 %0, %1;" : "=f"(y) : "f"(x));
    return y;
}

__global__ void __launch_bounds__(TPB) conv_sim_kernel(
    const float* __restrict__ omega,
    const float* __restrict__ Wh1, const float* __restrict__ bh1,
    const float* __restrict__ Wh2, const float* __restrict__ bh2,
    const float* __restrict__ Wr1, const float* __restrict__ br1,
    const float* __restrict__ Wr2, const float* __restrict__ br2,
    int N)
{
    const int i = blockIdx.x * blockDim.x + threadIdx.x;

    // Hoist all weights into registers (uniform address -> L1 broadcast, loop-invariant)
    float wh1[16], vbh1[4], wh2[4], wr1[9], vbr1[3], wr2[3];
    #pragma unroll
    for (int j = 0; j < 16; j++) wh1[j] = __ldg(&Wh1[j]);
    #pragma unroll
    for (int j = 0; j < 4; j++)  vbh1[j] = __ldg(&bh1[j]);
    #pragma unroll
    for (int j = 0; j < 4; j++)  wh2[j] = __ldg(&Wh2[j]);
    const float vbh2 = __ldg(&bh2[0]);
    #pragma unroll
    for (int j = 0; j < 9; j++)  wr1[j] = __ldg(&Wr1[j]);
    #pragma unroll
    for (int j = 0; j < 3; j++)  vbr1[j] = __ldg(&br1[j]);
    #pragma unroll
    for (int j = 0; j < 3; j++)  wr2[j] = __ldg(&Wr2[j]);
    const float vbr2 = __ldg(&br2[0]);

    float cost = 0.0f;   // err + eff for this task
    float nor_acc = 0.0f;

    if (i < N) {
        const float t0 = omega[i];       // omega[0, i]
        const float t1 = omega[N + i];   // omega[1, i]

        float s0 = 0.0f, s1 = 0.0f;
        float err = 0.0f, eff = 0.0f, nor = 0.0f;

        #pragma unroll 2
        for (int st = 0; st < N_STEPS - 1; st++) {
            const float e0 = t0 - s0;
            const float e1 = t1 - s1;
            err = fmaf(10.0f * e0, e0, err);
            err = fmaf(e1, e1, err);
            const float zt = fmaf(0.1f, e1, e0);

            // human MLP: xh = [t0, t1, s0, s1]; tanh both layers
            float h0 = vbh1[0], h1 = vbh1[1], h2 = vbh1[2], h3 = vbh1[3];
            h0 = fmaf(wh1[0],  t0, h0); h0 = fmaf(wh1[1],  t1, h0);
            h0 = fmaf(wh1[2],  s0, h0); h0 = fmaf(wh1[3],  s1, h0);
            h1 = fmaf(wh1[4],  t0, h1); h1 = fmaf(wh1[5],  t1, h1);
            h1 = fmaf(wh1[6],  s0, h1); h1 = fmaf(wh1[7],  s1, h1);
            h2 = fmaf(wh1[8],  t0, h2); h2 = fmaf(wh1[9],  t1, h2);
            h2 = fmaf(wh1[10], s0, h2); h2 = fmaf(wh1[11], s1, h2);
            h3 = fmaf(wh1[12], t0, h3); h3 = fmaf(wh1[13], t1, h3);
            h3 = fmaf(wh1[14], s0, h3); h3 = fmaf(wh1[15], s1, h3);
            h0 = fast_tanh(h0); h1 = fast_tanh(h1);
            h2 = fast_tanh(h2); h3 = fast_tanh(h3);

            float zz = vbh2;
            zz = fmaf(wh2[0], h0, zz); zz = fmaf(wh2[1], h1, zz);
            zz = fmaf(wh2[2], h2, zz); zz = fmaf(wh2[3], h3, zz);
            const float z = fast_tanh(zz);

            // robot MLP: xr = [s0, s1, z]; tanh hidden, linear out
            float r0 = vbr1[0], r1 = vbr1[1], r2 = vbr1[2];
            r0 = fmaf(wr1[0], s0, r0); r0 = fmaf(wr1[1], s1, r0); r0 = fmaf(wr1[2], z, r0);
            r1 = fmaf(wr1[3], s0, r1); r1 = fmaf(wr1[4], s1, r1); r1 = fmaf(wr1[5], z, r1);
            r2 = fmaf(wr1[6], s0, r2); r2 = fmaf(wr1[7], s1, r2); r2 = fmaf(wr1[8], z, r2);
            r0 = fast_tanh(r0); r1 = fast_tanh(r1); r2 = fast_tanh(r2);

            float a = vbr2;
            a = fmaf(wr2[0], r0, a); a = fmaf(wr2[1], r1, a); a = fmaf(wr2[2], r2, a);

            // s_next = [s0 + dt*s1, s1 + dt*a]
            const float ns0 = fmaf(DT, s1, s0);
            const float ns1 = fmaf(DT, a, s1);
            s0 = ns0; s1 = ns1;

            eff += (fabsf(z) > 0.01f) ? 1.0f : 0.0f;
            const float d = zt - z;
            nor = fmaf(d, d, nor);
        }

        // final error term
        const float e0 = t0 - s0;
        const float e1 = t1 - s1;
        err = fmaf(10.0f * e0, e0, err);
        err = fmaf(e1, e1, err);

        cost = err + eff;
        nor_acc = nor;
    }

    // ---- deterministic block reduction ----
    #pragma unroll
    for (int off = 16; off > 0; off >>= 1) {
        cost    += __shfl_down_sync(0xffffffffu, cost, off);
        nor_acc += __shfl_down_sync(0xffffffffu, nor_acc, off);
    }
    __shared__ float sc[TPB / 32], sn[TPB / 32];
    const int lane = threadIdx.x & 31;
    const int warp = threadIdx.x >> 5;
    if (lane == 0) { sc[warp] = cost; sn[warp] = nor_acc; }
    __syncthreads();
    if (warp == 0) {
        cost    = (lane < TPB / 32) ? sc[lane] : 0.0f;
        nor_acc = (lane < TPB / 32) ? sn[lane] : 0.0f;
        #pragma unroll
        for (int off = (TPB / 32) >> 1; off > 0; off >>= 1) {
            cost    += __shfl_down_sync(0xffffffffu, cost, off);
            nor_acc += __shfl_down_sync(0xffffffffu, nor_acc, off);
        }
        if (lane == 0) {
            g_partials[2 * blockIdx.x]     = cost;
            g_partials[2 * blockIdx.x + 1] = nor_acc;
        }
    }
}

__global__ void __launch_bounds__(TPB) conv_reduce_kernel(
    const float* __restrict__ alpha, float* __restrict__ out,
    int nblocks, float invN)
{
    float c = 0.0f, n = 0.0f;
    // fixed strided order -> deterministic
    for (int j = threadIdx.x; j < nblocks; j += TPB) {
        c += g_partials[2 * j];
        n += g_partials[2 * j + 1];
    }
    #pragma unroll
    for (int off = 16; off > 0; off >>= 1) {
        c += __shfl_down_sync(0xffffffffu, c, off);
        n += __shfl_down_sync(0xffffffffu, n, off);
    }
    __shared__ float sc[TPB / 32], sn[TPB / 32];
    const int lane = threadIdx.x & 31;
    const int warp = threadIdx.x >> 5;
    if (lane == 0) { sc[warp] = c; sn[warp] = n; }
    __syncthreads();
    if (warp == 0) {
        c = (lane < TPB / 32) ? sc[lane] : 0.0f;
        n = (lane < TPB / 32) ? sn[lane] : 0.0f;
        #pragma unroll
        for (int off = (TPB / 32) >> 1; off > 0; off >>= 1) {
            c += __shfl_down_sync(0xffffffffu, c, off);
            n += __shfl_down_sync(0xffffffffu, n, off);
        }
        if (lane == 0) {
            out[0] = c * invN + alpha[0] * (n * invN);
        }
    }
}

extern "C" void kernel_launch(void* const* d_in, const int* in_sizes, int n_in,
                              void* d_out, int out_size)
{
    const float* omega = (const float*)d_in[0];
    const float* Wh1   = (const float*)d_in[1];
    const float* bh1   = (const float*)d_in[2];
    const float* Wh2   = (const float*)d_in[3];
    const float* bh2   = (const float*)d_in[4];
    const float* Wr1   = (const float*)d_in[5];
    const float* br1   = (const float*)d_in[6];
    const float* Wr2   = (const float*)d_in[7];
    const float* br2   = (const float*)d_in[8];
    const float* alpha = (const float*)d_in[9];
    (void)n_in; (void)out_size;

    const int N = in_sizes[0] / 2;           // omega is [2, N]
    int blocks = (N + TPB - 1) / TPB;
    if (blocks > MAX_BLOCKS) blocks = MAX_BLOCKS;  // N=1M -> 4096, safe

    conv_sim_kernel<<<blocks, TPB>>>(omega, Wh1, bh1, Wh2, bh2,
                                     Wr1, br1, Wr2, br2, N);
    conv_reduce_kernel<<<1, TPB>>>(alpha, (float*)d_out, blocks, 1.0f / (float)N);
}